// round 8
// baseline (speedup 1.0000x reference)
#include <cuda_runtime.h>
#include <cuda_bf16.h>
#include <cstdint>

#define NN 100000
#define EE 1600000
#define IN_DIM 256
#define HID 128
#define NCLS 40
#define CAP 64

// ---------------- scratch ----------------------------------------------------
__device__ int   g_cnt[NN];
__device__ int   g_bkt[(size_t)NN * CAP];
__device__ float g_h[(size_t)NN * HID];
__device__ float g_a[(size_t)NN * HID];

// ---------------- preprocessing ----------------------------------------------
__global__ void zero_kernel() {
    int i = blockIdx.x * blockDim.x + threadIdx.x;
    if (i < NN) g_cnt[i] = 0;
}
__global__ void __launch_bounds__(256) fillb_kernel(
        const int* __restrict__ src, const int* __restrict__ dst) {
    int i = blockIdx.x * blockDim.x + threadIdx.x;
    int stride = gridDim.x * blockDim.x;
    for (; i < EE; i += stride) {
        int s = src[i];
        int d = dst[i];
        int pos = atomicAdd(&g_cnt[d], 1);
        if (pos < CAP) g_bkt[(size_t)d * CAP + pos] = s;
    }
}

__device__ __forceinline__ float dinv_of(int node) {
    return rsqrtf((float)(g_cnt[node] + 1));
}

// ---------------- mma.sync helpers --------------------------------------------
__device__ __forceinline__ void mma16816(float* c, const uint32_t* a,
                                         uint32_t b0, uint32_t b1) {
    asm volatile(
        "mma.sync.aligned.m16n8k16.row.col.f32.bf16.bf16.f32 "
        "{%0,%1,%2,%3}, {%4,%5,%6,%7}, {%8,%9}, {%0,%1,%2,%3};"
        : "+f"(c[0]), "+f"(c[1]), "+f"(c[2]), "+f"(c[3])
        : "r"(a[0]), "r"(a[1]), "r"(a[2]), "r"(a[3]), "r"(b0), "r"(b1));
}
__device__ __forceinline__ uint32_t pack_bf16(__nv_bfloat16 lo, __nv_bfloat16 hi) {
    __nv_bfloat162 p; p.x = lo; p.y = hi;
    return *(uint32_t*)&p;
}

// ---------------- HMMA bf16-split GEMM ----------------------------------------
// C[n,128] = dinv[row] * (A[n,K] @ W[K,128]); 3-term split, fp32 accum.
#define BKP 34

template <int K>
__global__ void __launch_bounds__(256) gemm_mma_kernel(
        const float* __restrict__ A, const float* __restrict__ W,
        float* __restrict__ C, int n) {
    __shared__ __nv_bfloat16 Ah[128][BKP], Al[128][BKP];
    __shared__ __nv_bfloat16 Bh[128][BKP], Bl[128][BKP];

    const int tid  = threadIdx.x;
    const int wid  = tid >> 5;
    const int lane = tid & 31;
    const int grp  = lane >> 2;
    const int q    = lane & 3;

    const int warp_m = wid & 3;
    const int warp_n = wid >> 2;
    const int m_base = warp_m * 32;
    const int n_base = warp_n * 64;
    const int block_row = blockIdx.x * 128;

    float c[2][8][4];
    #pragma unroll
    for (int mt = 0; mt < 2; mt++)
        #pragma unroll
        for (int nt = 0; nt < 8; nt++)
            #pragma unroll
            for (int j = 0; j < 4; j++) c[mt][nt][j] = 0.f;

    for (int k0 = 0; k0 < K; k0 += 32) {
        #pragma unroll
        for (int r = 0; r < 4; r++) {
            int idx = tid + r * 256;
            int row = idx >> 3;
            int c4  = idx & 7;
            int grow = block_row + row;
            float4 v = make_float4(0.f, 0.f, 0.f, 0.f);
            if (grow < n)
                v = *(const float4*)&A[(size_t)grow * K + k0 + c4 * 4];
            __nv_bfloat16 h0 = __float2bfloat16(v.x);
            __nv_bfloat16 h1 = __float2bfloat16(v.y);
            __nv_bfloat16 h2 = __float2bfloat16(v.z);
            __nv_bfloat16 h3 = __float2bfloat16(v.w);
            __nv_bfloat16 l0 = __float2bfloat16(v.x - __bfloat162float(h0));
            __nv_bfloat16 l1 = __float2bfloat16(v.y - __bfloat162float(h1));
            __nv_bfloat16 l2 = __float2bfloat16(v.z - __bfloat162float(h2));
            __nv_bfloat16 l3 = __float2bfloat16(v.w - __bfloat162float(h3));
            *(uint32_t*)&Ah[row][c4 * 4]     = pack_bf16(h0, h1);
            *(uint32_t*)&Ah[row][c4 * 4 + 2] = pack_bf16(h2, h3);
            *(uint32_t*)&Al[row][c4 * 4]     = pack_bf16(l0, l1);
            *(uint32_t*)&Al[row][c4 * 4 + 2] = pack_bf16(l2, l3);
        }
        #pragma unroll
        for (int r = 0; r < 4; r++) {
            int idx  = tid + r * 256;
            int krow = idx >> 5;
            int c4   = idx & 31;
            float4 v = *(const float4*)&W[(size_t)(k0 + krow) * 128 + c4 * 4];
            #pragma unroll
            for (int j = 0; j < 4; j++) {
                float w = (j == 0) ? v.x : (j == 1) ? v.y : (j == 2) ? v.z : v.w;
                __nv_bfloat16 h = __float2bfloat16(w);
                __nv_bfloat16 l = __float2bfloat16(w - __bfloat162float(h));
                Bh[c4 * 4 + j][krow] = h;
                Bl[c4 * 4 + j][krow] = l;
            }
        }
        __syncthreads();

        #pragma unroll
        for (int ks = 0; ks < 2; ks++) {
            const int kk = ks * 16;
            uint32_t ah[2][4], al[2][4];
            #pragma unroll
            for (int mt = 0; mt < 2; mt++) {
                int r0 = m_base + mt * 16 + grp;
                ah[mt][0] = *(const uint32_t*)&Ah[r0    ][kk + q * 2];
                ah[mt][1] = *(const uint32_t*)&Ah[r0 + 8][kk + q * 2];
                ah[mt][2] = *(const uint32_t*)&Ah[r0    ][kk + 8 + q * 2];
                ah[mt][3] = *(const uint32_t*)&Ah[r0 + 8][kk + 8 + q * 2];
                al[mt][0] = *(const uint32_t*)&Al[r0    ][kk + q * 2];
                al[mt][1] = *(const uint32_t*)&Al[r0 + 8][kk + q * 2];
                al[mt][2] = *(const uint32_t*)&Al[r0    ][kk + 8 + q * 2];
                al[mt][3] = *(const uint32_t*)&Al[r0 + 8][kk + 8 + q * 2];
            }
            #pragma unroll
            for (int nt = 0; nt < 8; nt++) {
                int cn = n_base + nt * 8 + grp;
                uint32_t bh0 = *(const uint32_t*)&Bh[cn][kk + q * 2];
                uint32_t bh1 = *(const uint32_t*)&Bh[cn][kk + 8 + q * 2];
                uint32_t bl0 = *(const uint32_t*)&Bl[cn][kk + q * 2];
                uint32_t bl1 = *(const uint32_t*)&Bl[cn][kk + 8 + q * 2];
                #pragma unroll
                for (int mt = 0; mt < 2; mt++) {
                    mma16816(c[mt][nt], ah[mt], bh0, bh1);
                    mma16816(c[mt][nt], ah[mt], bl0, bl1);
                    mma16816(c[mt][nt], al[mt], bh0, bh1);
                }
            }
        }
        __syncthreads();
    }

    #pragma unroll
    for (int mt = 0; mt < 2; mt++) {
        int row0 = block_row + m_base + mt * 16 + grp;
        int row1 = row0 + 8;
        float d0 = (row0 < n) ? dinv_of(row0) : 0.f;
        float d1 = (row1 < n) ? dinv_of(row1) : 0.f;
        #pragma unroll
        for (int nt = 0; nt < 8; nt++) {
            int col = n_base + nt * 8 + q * 2;
            if (row0 < n)
                *(float2*)&C[(size_t)row0 * 128 + col] =
                    make_float2(c[mt][nt][0] * d0, c[mt][nt][1] * d0);
            if (row1 < n)
                *(float2*)&C[(size_t)row1 * 128 + col] =
                    make_float2(c[mt][nt][2] * d1, c[mt][nt][3] * d1);
        }
    }
}

// ---------------- GEMM: C[n,40] = dinv[row] * (A[n,128] @ W[128,40]) --------
__global__ void __launch_bounds__(256) gemm40_kernel(
        const float* __restrict__ A, const float* __restrict__ W,
        float* __restrict__ C, int n) {
    __shared__ float Ws[128][NCLS];
    for (int i = threadIdx.x; i < 128 * NCLS; i += blockDim.x)
        Ws[i / NCLS][i % NCLS] = W[i];
    __syncthreads();

    int row = blockIdx.x * blockDim.x + threadIdx.x;
    if (row >= n) return;

    float acc[NCLS];
    #pragma unroll
    for (int c = 0; c < NCLS; c++) acc[c] = 0.f;

    const float4* a4 = (const float4*)(A + (size_t)row * 128);
    #pragma unroll 4
    for (int k4 = 0; k4 < 32; k4++) {
        float4 a = __ldg(&a4[k4]);
        int k = k4 * 4;
        #pragma unroll
        for (int c = 0; c < NCLS; c++) {
            acc[c] += a.x * Ws[k][c];
            acc[c] += a.y * Ws[k + 1][c];
            acc[c] += a.z * Ws[k + 2][c];
            acc[c] += a.w * Ws[k + 3][c];
        }
    }
    float d = dinv_of(row);
    float* out = C + (size_t)row * NCLS;
    #pragma unroll
    for (int c = 0; c < NCLS; c++) out[c] = acc[c] * d;
}

// ---------------- aggregation, 128 cols ---------------------------------------
// streaming data (bkt, out) uses evict-first hints; gathered h stays L2-hot.
template <bool RELU>
__global__ void __launch_bounds__(256) agg128_kernel(
        const float* __restrict__ h, const float* __restrict__ bias,
        float* __restrict__ out) {
    const int lane = threadIdx.x & 31;
    const int gw   = (blockIdx.x * 256 + threadIdx.x) >> 5;
    const int nw   = (gridDim.x * 256) >> 5;
    const float4 bv = ((const float4*)bias)[lane];
    const float4* __restrict__ h4 = (const float4*)h;

    for (int node = gw; node < NN; node += nw) {
        int rawcnt = g_cnt[node];
        int cnt = rawcnt > CAP ? CAP : rawcnt;
        const int* __restrict__ bkt = g_bkt + (size_t)node * CAP;

        float4 acc = __ldg(h4 + (size_t)node * 32 + lane);   // self-loop
        for (int k0 = 0; k0 < cnt; k0 += 32) {
            int idx = k0 + lane;
            int sk = (idx < cnt) ? __ldcs(&bkt[idx]) : 0;
            int m = cnt - k0; if (m > 32) m = 32;
            int j = 0;
            for (; j + 4 <= m; j += 4) {
                int s0 = __shfl_sync(0xFFFFFFFFu, sk, j);
                int s1 = __shfl_sync(0xFFFFFFFFu, sk, j + 1);
                int s2 = __shfl_sync(0xFFFFFFFFu, sk, j + 2);
                int s3 = __shfl_sync(0xFFFFFFFFu, sk, j + 3);
                float4 v0 = __ldg(h4 + (size_t)s0 * 32 + lane);
                float4 v1 = __ldg(h4 + (size_t)s1 * 32 + lane);
                float4 v2 = __ldg(h4 + (size_t)s2 * 32 + lane);
                float4 v3 = __ldg(h4 + (size_t)s3 * 32 + lane);
                acc.x += (v0.x + v1.x) + (v2.x + v3.x);
                acc.y += (v0.y + v1.y) + (v2.y + v3.y);
                acc.z += (v0.z + v1.z) + (v2.z + v3.z);
                acc.w += (v0.w + v1.w) + (v2.w + v3.w);
            }
            for (; j < m; j++) {
                int s = __shfl_sync(0xFFFFFFFFu, sk, j);
                float4 v = __ldg(h4 + (size_t)s * 32 + lane);
                acc.x += v.x; acc.y += v.y; acc.z += v.z; acc.w += v.w;
            }
        }
        const float d = rsqrtf((float)(rawcnt + 1));
        float4 r;
        r.x = fmaf(acc.x, d, bv.x);
        r.y = fmaf(acc.y, d, bv.y);
        r.z = fmaf(acc.z, d, bv.z);
        r.w = fmaf(acc.w, d, bv.w);
        if (RELU) {
            r.x = fmaxf(r.x, 0.f); r.y = fmaxf(r.y, 0.f);
            r.z = fmaxf(r.z, 0.f); r.w = fmaxf(r.w, 0.f);
        }
        __stcs(&((float4*)out)[(size_t)node * 32 + lane], r);
    }
}

// ---------------- aggregation, 40 cols ---------------------------------------
__global__ void __launch_bounds__(256) agg40_kernel(
        const float* __restrict__ h, const float* __restrict__ bias,
        float* __restrict__ out) {
    const int lane = threadIdx.x & 31;
    const int gw   = (blockIdx.x * 256 + threadIdx.x) >> 5;
    const int nw   = (gridDim.x * 256) >> 5;
    const bool act = lane < 20;
    float2 bv = make_float2(0.f, 0.f);
    if (act) bv = ((const float2*)bias)[lane];

    for (int node = gw; node < NN; node += nw) {
        int rawcnt = g_cnt[node];
        int cnt = rawcnt > CAP ? CAP : rawcnt;
        const int* __restrict__ bkt = g_bkt + (size_t)node * CAP;

        float2 acc = make_float2(0.f, 0.f);
        if (act) acc = __ldg((const float2*)(h + (size_t)node * NCLS) + lane);

        for (int k0 = 0; k0 < cnt; k0 += 32) {
            int idx = k0 + lane;
            int sk = (idx < cnt) ? __ldcs(&bkt[idx]) : 0;
            int m = cnt - k0; if (m > 32) m = 32;
            int j = 0;
            for (; j + 4 <= m; j += 4) {
                int s0 = __shfl_sync(0xFFFFFFFFu, sk, j);
                int s1 = __shfl_sync(0xFFFFFFFFu, sk, j + 1);
                int s2 = __shfl_sync(0xFFFFFFFFu, sk, j + 2);
                int s3 = __shfl_sync(0xFFFFFFFFu, sk, j + 3);
                if (act) {
                    float2 v0 = __ldg((const float2*)(h + (size_t)s0 * NCLS) + lane);
                    float2 v1 = __ldg((const float2*)(h + (size_t)s1 * NCLS) + lane);
                    float2 v2 = __ldg((const float2*)(h + (size_t)s2 * NCLS) + lane);
                    float2 v3 = __ldg((const float2*)(h + (size_t)s3 * NCLS) + lane);
                    acc.x += (v0.x + v1.x) + (v2.x + v3.x);
                    acc.y += (v0.y + v1.y) + (v2.y + v3.y);
                }
            }
            for (; j < m; j++) {
                int s = __shfl_sync(0xFFFFFFFFu, sk, j);
                if (act) {
                    float2 v = __ldg((const float2*)(h + (size_t)s * NCLS) + lane);
                    acc.x += v.x; acc.y += v.y;
                }
            }
        }
        if (act) {
            const float d = rsqrtf((float)(rawcnt + 1));
            float2 r;
            r.x = fmaf(acc.x, d, bv.x);
            r.y = fmaf(acc.y, d, bv.y);
            __stcs(&((float2*)(out + (size_t)node * NCLS))[lane], r);
        }
    }
}

// ---------------- launch -----------------------------------------------------
extern "C" void kernel_launch(void* const* d_in, const int* in_sizes, int n_in,
                              void* d_out, int out_size) {
    const float* x   = (const float*)d_in[0];
    const int*   ei  = (const int*)d_in[1];
    const float* W1  = (const float*)d_in[2];
    const float* b1  = (const float*)d_in[3];
    const float* W2  = (const float*)d_in[4];
    const float* b2  = (const float*)d_in[5];
    const float* W3  = (const float*)d_in[6];
    const float* b3  = (const float*)d_in[7];
    float* out = (float*)d_out;

    const int* src = ei;
    const int* dst = ei + EE;

    const int AGG_BLOCKS  = 148 * 16;
    const int GEMM_BLOCKS = (NN + 127) / 128;

    zero_kernel<<<(NN + 255) / 256, 256>>>();                        // 1
    fillb_kernel<<<2048, 256>>>(src, dst);                           // 2
    gemm_mma_kernel<IN_DIM><<<GEMM_BLOCKS, 256>>>(x, W1, g_h, NN);   // 3
    agg128_kernel<true><<<AGG_BLOCKS, 256>>>(g_h, b1, g_a);          // 4 <-- profiled
    gemm_mma_kernel<HID><<<GEMM_BLOCKS, 256>>>(g_a, W2, g_h, NN);    // 5
    agg128_kernel<true><<<AGG_BLOCKS, 256>>>(g_h, b2, g_a);          // 6
    gemm40_kernel<<<(NN + 255) / 256, 256>>>(g_a, W3, g_h, NN);      // 7
    agg40_kernel<<<AGG_BLOCKS, 256>>>(g_h, b3, out);                 // 8
}

// round 9
// speedup vs baseline: 1.0151x; 1.0151x over previous
#include <cuda_runtime.h>
#include <cuda_bf16.h>
#include <cstdint>

#define NN 100000
#define EE 1600000
#define IN_DIM 256
#define HID 128
#define NCLS 40
#define CAP 64

// ---------------- scratch ----------------------------------------------------
__device__ int   g_cnt[NN];
__device__ int   g_bkt[(size_t)NN * CAP];
__device__ float g_h[(size_t)NN * HID];   // layer-1 / layer-3 gemm outputs
__device__ float g_a[(size_t)NN * HID];   // fused1 output (layer-2 h)

// ---------------- preprocessing ----------------------------------------------
__global__ void zero_kernel() {
    int i = blockIdx.x * blockDim.x + threadIdx.x;
    if (i < NN) g_cnt[i] = 0;
}
__global__ void __launch_bounds__(256) fillb_kernel(
        const int* __restrict__ src, const int* __restrict__ dst) {
    int i = blockIdx.x * blockDim.x + threadIdx.x;
    int stride = gridDim.x * blockDim.x;
    for (; i < EE; i += stride) {
        int s = src[i];
        int d = dst[i];
        int pos = atomicAdd(&g_cnt[d], 1);
        if (pos < CAP) g_bkt[(size_t)d * CAP + pos] = s;
    }
}

// ---------------- mma.sync helpers --------------------------------------------
__device__ __forceinline__ void mma16816(float* c, const uint32_t* a,
                                         uint32_t b0, uint32_t b1) {
    asm volatile(
        "mma.sync.aligned.m16n8k16.row.col.f32.bf16.bf16.f32 "
        "{%0,%1,%2,%3}, {%4,%5,%6,%7}, {%8,%9}, {%0,%1,%2,%3};"
        : "+f"(c[0]), "+f"(c[1]), "+f"(c[2]), "+f"(c[3])
        : "r"(a[0]), "r"(a[1]), "r"(a[2]), "r"(a[3]), "r"(b0), "r"(b1));
}
__device__ __forceinline__ uint32_t pack_bf16(__nv_bfloat16 lo, __nv_bfloat16 hi) {
    __nv_bfloat162 p; p.x = lo; p.y = hi;
    return *(uint32_t*)&p;
}

// ---------------- HMMA bf16-split GEMM (global A) -----------------------------
// C[n,128] = rsqrt(cnt+1)[row] * (A[n,K] @ W[K,128]); 3-term split, fp32 accum.
#define BKP 34

template <int K>
__global__ void __launch_bounds__(256) gemm_mma_kernel(
        const float* __restrict__ A, const float* __restrict__ W,
        float* __restrict__ C, int n) {
    __shared__ __nv_bfloat16 Ah[128][BKP], Al[128][BKP];
    __shared__ __nv_bfloat16 Bh[128][BKP], Bl[128][BKP];

    const int tid  = threadIdx.x;
    const int wid  = tid >> 5;
    const int lane = tid & 31;
    const int grp  = lane >> 2;
    const int q    = lane & 3;

    const int warp_m = wid & 3;
    const int warp_n = wid >> 2;
    const int m_base = warp_m * 32;
    const int n_base = warp_n * 64;
    const int block_row = blockIdx.x * 128;

    float c[2][8][4];
    #pragma unroll
    for (int mt = 0; mt < 2; mt++)
        #pragma unroll
        for (int nt = 0; nt < 8; nt++)
            #pragma unroll
            for (int j = 0; j < 4; j++) c[mt][nt][j] = 0.f;

    for (int k0 = 0; k0 < K; k0 += 32) {
        #pragma unroll
        for (int r = 0; r < 4; r++) {
            int idx = tid + r * 256;
            int row = idx >> 3;
            int c4  = idx & 7;
            int grow = block_row + row;
            float4 v = make_float4(0.f, 0.f, 0.f, 0.f);
            if (grow < n)
                v = *(const float4*)&A[(size_t)grow * K + k0 + c4 * 4];
            __nv_bfloat16 h0 = __float2bfloat16(v.x);
            __nv_bfloat16 h1 = __float2bfloat16(v.y);
            __nv_bfloat16 h2 = __float2bfloat16(v.z);
            __nv_bfloat16 h3 = __float2bfloat16(v.w);
            __nv_bfloat16 l0 = __float2bfloat16(v.x - __bfloat162float(h0));
            __nv_bfloat16 l1 = __float2bfloat16(v.y - __bfloat162float(h1));
            __nv_bfloat16 l2 = __float2bfloat16(v.z - __bfloat162float(h2));
            __nv_bfloat16 l3 = __float2bfloat16(v.w - __bfloat162float(h3));
            *(uint32_t*)&Ah[row][c4 * 4]     = pack_bf16(h0, h1);
            *(uint32_t*)&Ah[row][c4 * 4 + 2] = pack_bf16(h2, h3);
            *(uint32_t*)&Al[row][c4 * 4]     = pack_bf16(l0, l1);
            *(uint32_t*)&Al[row][c4 * 4 + 2] = pack_bf16(l2, l3);
        }
        #pragma unroll
        for (int r = 0; r < 4; r++) {
            int idx  = tid + r * 256;
            int krow = idx >> 5;
            int c4   = idx & 31;
            float4 v = *(const float4*)&W[(size_t)(k0 + krow) * 128 + c4 * 4];
            #pragma unroll
            for (int j = 0; j < 4; j++) {
                float w = (j == 0) ? v.x : (j == 1) ? v.y : (j == 2) ? v.z : v.w;
                __nv_bfloat16 h = __float2bfloat16(w);
                __nv_bfloat16 l = __float2bfloat16(w - __bfloat162float(h));
                Bh[c4 * 4 + j][krow] = h;
                Bl[c4 * 4 + j][krow] = l;
            }
        }
        __syncthreads();

        #pragma unroll
        for (int ks = 0; ks < 2; ks++) {
            const int kk = ks * 16;
            uint32_t ah[2][4], al[2][4];
            #pragma unroll
            for (int mt = 0; mt < 2; mt++) {
                int r0 = m_base + mt * 16 + grp;
                ah[mt][0] = *(const uint32_t*)&Ah[r0    ][kk + q * 2];
                ah[mt][1] = *(const uint32_t*)&Ah[r0 + 8][kk + q * 2];
                ah[mt][2] = *(const uint32_t*)&Ah[r0    ][kk + 8 + q * 2];
                ah[mt][3] = *(const uint32_t*)&Ah[r0 + 8][kk + 8 + q * 2];
                al[mt][0] = *(const uint32_t*)&Al[r0    ][kk + q * 2];
                al[mt][1] = *(const uint32_t*)&Al[r0 + 8][kk + q * 2];
                al[mt][2] = *(const uint32_t*)&Al[r0    ][kk + 8 + q * 2];
                al[mt][3] = *(const uint32_t*)&Al[r0 + 8][kk + 8 + q * 2];
            }
            #pragma unroll
            for (int nt = 0; nt < 8; nt++) {
                int cn = n_base + nt * 8 + grp;
                uint32_t bh0 = *(const uint32_t*)&Bh[cn][kk + q * 2];
                uint32_t bh1 = *(const uint32_t*)&Bh[cn][kk + 8 + q * 2];
                uint32_t bl0 = *(const uint32_t*)&Bl[cn][kk + q * 2];
                uint32_t bl1 = *(const uint32_t*)&Bl[cn][kk + 8 + q * 2];
                #pragma unroll
                for (int mt = 0; mt < 2; mt++) {
                    mma16816(c[mt][nt], ah[mt], bh0, bh1);
                    mma16816(c[mt][nt], ah[mt], bl0, bl1);
                    mma16816(c[mt][nt], al[mt], bh0, bh1);
                }
            }
        }
        __syncthreads();
    }

    #pragma unroll
    for (int mt = 0; mt < 2; mt++) {
        int row0 = block_row + m_base + mt * 16 + grp;
        int row1 = row0 + 8;
        float d0 = (row0 < n) ? rsqrtf((float)(g_cnt[row0] + 1)) : 0.f;
        float d1 = (row1 < n) ? rsqrtf((float)(g_cnt[row1] + 1)) : 0.f;
        #pragma unroll
        for (int nt = 0; nt < 8; nt++) {
            int col = n_base + nt * 8 + q * 2;
            if (row0 < n)
                *(float2*)&C[(size_t)row0 * 128 + col] =
                    make_float2(c[mt][nt][0] * d0, c[mt][nt][1] * d0);
            if (row1 < n)
                *(float2*)&C[(size_t)row1 * 128 + col] =
                    make_float2(c[mt][nt][2] * d1, c[mt][nt][3] * d1);
        }
    }
}

// ---------------- warp aggregation of one node (128 cols) into float4 --------
__device__ __forceinline__ float4 agg_node128(
        const float4* __restrict__ h4, int node, int lane, const float4& bv) {
    int rawcnt = g_cnt[node];
    int cnt = rawcnt > CAP ? CAP : rawcnt;
    const int* __restrict__ bkt = g_bkt + (size_t)node * CAP;

    float4 acc = __ldg(h4 + (size_t)node * 32 + lane);   // self-loop
    for (int k0 = 0; k0 < cnt; k0 += 32) {
        int idx = k0 + lane;
        int sk = (idx < cnt) ? __ldg(&bkt[idx]) : 0;
        int m = cnt - k0; if (m > 32) m = 32;
        int j = 0;
        for (; j + 4 <= m; j += 4) {
            int s0 = __shfl_sync(0xFFFFFFFFu, sk, j);
            int s1 = __shfl_sync(0xFFFFFFFFu, sk, j + 1);
            int s2 = __shfl_sync(0xFFFFFFFFu, sk, j + 2);
            int s3 = __shfl_sync(0xFFFFFFFFu, sk, j + 3);
            float4 v0 = __ldg(h4 + (size_t)s0 * 32 + lane);
            float4 v1 = __ldg(h4 + (size_t)s1 * 32 + lane);
            float4 v2 = __ldg(h4 + (size_t)s2 * 32 + lane);
            float4 v3 = __ldg(h4 + (size_t)s3 * 32 + lane);
            acc.x += (v0.x + v1.x) + (v2.x + v3.x);
            acc.y += (v0.y + v1.y) + (v2.y + v3.y);
            acc.z += (v0.z + v1.z) + (v2.z + v3.z);
            acc.w += (v0.w + v1.w) + (v2.w + v3.w);
        }
        for (; j < m; j++) {
            int s = __shfl_sync(0xFFFFFFFFu, sk, j);
            float4 v = __ldg(h4 + (size_t)s * 32 + lane);
            acc.x += v.x; acc.y += v.y; acc.z += v.z; acc.w += v.w;
        }
    }
    const float d = rsqrtf((float)(rawcnt + 1));
    float4 r;
    r.x = fmaxf(fmaf(acc.x, d, bv.x), 0.f);
    r.y = fmaxf(fmaf(acc.y, d, bv.y), 0.f);
    r.z = fmaxf(fmaf(acc.z, d, bv.z), 0.f);
    r.w = fmaxf(fmaf(acc.w, d, bv.w), 0.f);
    return r;
}

// ---------------- fused1: agg(h,b) -> smem A -> HMMA x W -> C (prescaled) ----
// dynamic smem: As float[128][132] | Ah/Al/Bh/Bl bf16[128][34]
#define F1_AS   0
#define F1_AH   67584
#define F1_AL   (67584 + 8704)
#define F1_BH   (67584 + 2 * 8704)
#define F1_BL   (67584 + 3 * 8704)
#define F1_SMEM (67584 + 4 * 8704)

__global__ void __launch_bounds__(256) fused_agg_gemm128(
        const float* __restrict__ h, const float* __restrict__ bias,
        const float* __restrict__ W, float* __restrict__ C, int n) {
    extern __shared__ char sm[];
    float* As = (float*)(sm + F1_AS);                 // [128][132]
    __nv_bfloat16 (*Ah)[BKP] = (__nv_bfloat16(*)[BKP])(sm + F1_AH);
    __nv_bfloat16 (*Al)[BKP] = (__nv_bfloat16(*)[BKP])(sm + F1_AL);
    __nv_bfloat16 (*Bh)[BKP] = (__nv_bfloat16(*)[BKP])(sm + F1_BH);
    __nv_bfloat16 (*Bl)[BKP] = (__nv_bfloat16(*)[BKP])(sm + F1_BL);

    const int tid  = threadIdx.x;
    const int wid  = tid >> 5;
    const int lane = tid & 31;
    const int block_row = blockIdx.x * 128;
    const float4* __restrict__ h4 = (const float4*)h;
    const float4 bv = ((const float4*)bias)[lane];

    // ---- phase A: aggregate 128 rows into As (relu'd activations) ----
    for (int t = 0; t < 16; t++) {
        int nl = wid * 16 + t;
        int node = block_row + nl;
        float4 r = make_float4(0.f, 0.f, 0.f, 0.f);
        if (node < n) r = agg_node128(h4, node, lane, bv);
        *(float4*)&As[nl * 132 + lane * 4] = r;
    }
    __syncthreads();

    // ---- phase B: HMMA bf16-split GEMM, A from smem ----
    const int grp = lane >> 2;
    const int q   = lane & 3;
    const int warp_m = wid & 3;
    const int warp_n = wid >> 2;
    const int m_base = warp_m * 32;
    const int n_base = warp_n * 64;

    float c[2][8][4];
    #pragma unroll
    for (int mt = 0; mt < 2; mt++)
        #pragma unroll
        for (int nt = 0; nt < 8; nt++)
            #pragma unroll
            for (int j = 0; j < 4; j++) c[mt][nt][j] = 0.f;

    for (int k0 = 0; k0 < 128; k0 += 32) {
        #pragma unroll
        for (int r = 0; r < 4; r++) {
            int idx = tid + r * 256;
            int row = idx >> 3;
            int c4  = idx & 7;
            float4 v = *(const float4*)&As[row * 132 + k0 + c4 * 4];
            __nv_bfloat16 h0 = __float2bfloat16(v.x);
            __nv_bfloat16 h1 = __float2bfloat16(v.y);
            __nv_bfloat16 h2 = __float2bfloat16(v.z);
            __nv_bfloat16 h3 = __float2bfloat16(v.w);
            __nv_bfloat16 l0 = __float2bfloat16(v.x - __bfloat162float(h0));
            __nv_bfloat16 l1 = __float2bfloat16(v.y - __bfloat162float(h1));
            __nv_bfloat16 l2 = __float2bfloat16(v.z - __bfloat162float(h2));
            __nv_bfloat16 l3 = __float2bfloat16(v.w - __bfloat162float(h3));
            *(uint32_t*)&Ah[row][c4 * 4]     = pack_bf16(h0, h1);
            *(uint32_t*)&Ah[row][c4 * 4 + 2] = pack_bf16(h2, h3);
            *(uint32_t*)&Al[row][c4 * 4]     = pack_bf16(l0, l1);
            *(uint32_t*)&Al[row][c4 * 4 + 2] = pack_bf16(l2, l3);
        }
        #pragma unroll
        for (int r = 0; r < 4; r++) {
            int idx  = tid + r * 256;
            int krow = idx >> 5;
            int c4   = idx & 31;
            float4 v = *(const float4*)&W[(size_t)(k0 + krow) * 128 + c4 * 4];
            #pragma unroll
            for (int j = 0; j < 4; j++) {
                float w = (j == 0) ? v.x : (j == 1) ? v.y : (j == 2) ? v.z : v.w;
                __nv_bfloat16 hh = __float2bfloat16(w);
                __nv_bfloat16 ll = __float2bfloat16(w - __bfloat162float(hh));
                Bh[c4 * 4 + j][krow] = hh;
                Bl[c4 * 4 + j][krow] = ll;
            }
        }
        __syncthreads();

        #pragma unroll
        for (int ks = 0; ks < 2; ks++) {
            const int kk = ks * 16;
            uint32_t ah[2][4], al[2][4];
            #pragma unroll
            for (int mt = 0; mt < 2; mt++) {
                int r0 = m_base + mt * 16 + grp;
                ah[mt][0] = *(const uint32_t*)&Ah[r0    ][kk + q * 2];
                ah[mt][1] = *(const uint32_t*)&Ah[r0 + 8][kk + q * 2];
                ah[mt][2] = *(const uint32_t*)&Ah[r0    ][kk + 8 + q * 2];
                ah[mt][3] = *(const uint32_t*)&Ah[r0 + 8][kk + 8 + q * 2];
                al[mt][0] = *(const uint32_t*)&Al[r0    ][kk + q * 2];
                al[mt][1] = *(const uint32_t*)&Al[r0 + 8][kk + q * 2];
                al[mt][2] = *(const uint32_t*)&Al[r0    ][kk + 8 + q * 2];
                al[mt][3] = *(const uint32_t*)&Al[r0 + 8][kk + 8 + q * 2];
            }
            #pragma unroll
            for (int nt = 0; nt < 8; nt++) {
                int cn = n_base + nt * 8 + grp;
                uint32_t bh0 = *(const uint32_t*)&Bh[cn][kk + q * 2];
                uint32_t bh1 = *(const uint32_t*)&Bh[cn][kk + 8 + q * 2];
                uint32_t bl0 = *(const uint32_t*)&Bl[cn][kk + q * 2];
                uint32_t bl1 = *(const uint32_t*)&Bl[cn][kk + 8 + q * 2];
                #pragma unroll
                for (int mt = 0; mt < 2; mt++) {
                    mma16816(c[mt][nt], ah[mt], bh0, bh1);
                    mma16816(c[mt][nt], ah[mt], bl0, bl1);
                    mma16816(c[mt][nt], al[mt], bh0, bh1);
                }
            }
        }
        __syncthreads();
    }

    #pragma unroll
    for (int mt = 0; mt < 2; mt++) {
        int row0 = block_row + m_base + mt * 16 + grp;
        int row1 = row0 + 8;
        float d0 = (row0 < n) ? rsqrtf((float)(g_cnt[row0] + 1)) : 0.f;
        float d1 = (row1 < n) ? rsqrtf((float)(g_cnt[row1] + 1)) : 0.f;
        #pragma unroll
        for (int nt = 0; nt < 8; nt++) {
            int col = n_base + nt * 8 + q * 2;
            if (row0 < n)
                *(float2*)&C[(size_t)row0 * 128 + col] =
                    make_float2(c[mt][nt][0] * d0, c[mt][nt][1] * d0);
            if (row1 < n)
                *(float2*)&C[(size_t)row1 * 128 + col] =
                    make_float2(c[mt][nt][2] * d1, c[mt][nt][3] * d1);
        }
    }
}

// ---------------- fused2: agg(h,b) -> smem A -> x W3 (FFMA) -> C[n,40] -------
#define F2_AS   0
#define F2_WS   67584
#define F2_SMEM (67584 + 128 * NCLS * 4)

__global__ void __launch_bounds__(256) fused_agg_gemm40(
        const float* __restrict__ h, const float* __restrict__ bias,
        const float* __restrict__ W, float* __restrict__ C, int n) {
    extern __shared__ char sm[];
    float* As = (float*)(sm + F2_AS);     // [128][132]
    float* Ws = (float*)(sm + F2_WS);     // [128][40]

    const int tid  = threadIdx.x;
    const int wid  = tid >> 5;
    const int lane = tid & 31;
    const int block_row = blockIdx.x * 128;
    const float4* __restrict__ h4 = (const float4*)h;
    const float4 bv = ((const float4*)bias)[lane];

    for (int i = tid; i < 128 * NCLS; i += 256)
        Ws[i] = W[i];

    // ---- phase A: aggregate ----
    for (int t = 0; t < 16; t++) {
        int nl = wid * 16 + t;
        int node = block_row + nl;
        float4 r = make_float4(0.f, 0.f, 0.f, 0.f);
        if (node < n) r = agg_node128(h4, node, lane, bv);
        *(float4*)&As[nl * 132 + lane * 4] = r;
    }
    __syncthreads();

    // ---- phase B: 128x40 gemm, 2 threads per row ----
    const int row  = tid >> 1;
    const int half = tid & 1;
    const int col0 = half * 20;

    float acc[20];
    #pragma unroll
    for (int c = 0; c < 20; c++) acc[c] = 0.f;

    const float* arow = &As[row * 132];
    for (int k4 = 0; k4 < 32; k4++) {
        float4 a = *(const float4*)&arow[k4 * 4];
        int k = k4 * 4;
        #pragma unroll
        for (int c = 0; c < 20; c++) {
            acc[c] += a.x * Ws[(k    ) * NCLS + col0 + c];
            acc[c] += a.y * Ws[(k + 1) * NCLS + col0 + c];
            acc[c] += a.z * Ws[(k + 2) * NCLS + col0 + c];
            acc[c] += a.w * Ws[(k + 3) * NCLS + col0 + c];
        }
    }

    int grow = block_row + row;
    if (grow < n) {
        float d = rsqrtf((float)(g_cnt[grow] + 1));
        float* o = &C[(size_t)grow * NCLS + col0];
        #pragma unroll
        for (int c = 0; c < 20; c++) o[c] = acc[c] * d;
    }
}

// ---------------- aggregation, 40 cols (final) --------------------------------
__global__ void __launch_bounds__(256) agg40_kernel(
        const float* __restrict__ h, const float* __restrict__ bias,
        float* __restrict__ out) {
    const int lane = threadIdx.x & 31;
    const int gw   = (blockIdx.x * 256 + threadIdx.x) >> 5;
    const int nw   = (gridDim.x * 256) >> 5;
    const bool act = lane < 20;
    float2 bv = make_float2(0.f, 0.f);
    if (act) bv = ((const float2*)bias)[lane];

    for (int node = gw; node < NN; node += nw) {
        int rawcnt = g_cnt[node];
        int cnt = rawcnt > CAP ? CAP : rawcnt;
        const int* __restrict__ bkt = g_bkt + (size_t)node * CAP;

        float2 acc = make_float2(0.f, 0.f);
        if (act) acc = __ldg((const float2*)(h + (size_t)node * NCLS) + lane);

        for (int k0 = 0; k0 < cnt; k0 += 32) {
            int idx = k0 + lane;
            int sk = (idx < cnt) ? __ldg(&bkt[idx]) : 0;
            int m = cnt - k0; if (m > 32) m = 32;
            int j = 0;
            for (; j + 4 <= m; j += 4) {
                int s0 = __shfl_sync(0xFFFFFFFFu, sk, j);
                int s1 = __shfl_sync(0xFFFFFFFFu, sk, j + 1);
                int s2 = __shfl_sync(0xFFFFFFFFu, sk, j + 2);
                int s3 = __shfl_sync(0xFFFFFFFFu, sk, j + 3);
                if (act) {
                    float2 v0 = __ldg((const float2*)(h + (size_t)s0 * NCLS) + lane);
                    float2 v1 = __ldg((const float2*)(h + (size_t)s1 * NCLS) + lane);
                    float2 v2 = __ldg((const float2*)(h + (size_t)s2 * NCLS) + lane);
                    float2 v3 = __ldg((const float2*)(h + (size_t)s3 * NCLS) + lane);
                    acc.x += (v0.x + v1.x) + (v2.x + v3.x);
                    acc.y += (v0.y + v1.y) + (v2.y + v3.y);
                }
            }
            for (; j < m; j++) {
                int s = __shfl_sync(0xFFFFFFFFu, sk, j);
                if (act) {
                    float2 v = __ldg((const float2*)(h + (size_t)s * NCLS) + lane);
                    acc.x += v.x; acc.y += v.y;
                }
            }
        }
        if (act) {
            const float d = rsqrtf((float)(rawcnt + 1));
            float2 r;
            r.x = fmaf(acc.x, d, bv.x);
            r.y = fmaf(acc.y, d, bv.y);
            ((float2*)(out + (size_t)node * NCLS))[lane] = r;
        }
    }
}

// ---------------- launch -----------------------------------------------------
extern "C" void kernel_launch(void* const* d_in, const int* in_sizes, int n_in,
                              void* d_out, int out_size) {
    const float* x   = (const float*)d_in[0];
    const int*   ei  = (const int*)d_in[1];
    const float* W1  = (const float*)d_in[2];
    const float* b1  = (const float*)d_in[3];
    const float* W2  = (const float*)d_in[4];
    const float* b2  = (const float*)d_in[5];
    const float* W3  = (const float*)d_in[6];
    const float* b3  = (const float*)d_in[7];
    float* out = (float*)d_out;

    const int* src = ei;
    const int* dst = ei + EE;

    static bool attr_done = false;
    if (!attr_done) {
        cudaFuncSetAttribute(fused_agg_gemm128,
                             cudaFuncAttributeMaxDynamicSharedMemorySize, F1_SMEM);
        cudaFuncSetAttribute(fused_agg_gemm40,
                             cudaFuncAttributeMaxDynamicSharedMemorySize, F2_SMEM);
        attr_done = true;
    }

    const int GEMM_BLOCKS = (NN + 127) / 128;

    zero_kernel<<<(NN + 255) / 256, 256>>>();                          // 1
    fillb_kernel<<<2048, 256>>>(src, dst);                             // 2
    gemm_mma_kernel<IN_DIM><<<GEMM_BLOCKS, 256>>>(x, W1, g_h, NN);     // 3
    fused_agg_gemm128<<<GEMM_BLOCKS, 256, F1_SMEM>>>(g_h, b1, W2, g_a, NN); // 4 <-- profiled
    fused_agg_gemm40<<<GEMM_BLOCKS, 256, F2_SMEM>>>(g_a, b2, W3, g_h, NN);  // 5
    agg40_kernel<<<148 * 16, 256>>>(g_h, b3, out);                     // 6
}